// round 15
// baseline (speedup 1.0000x reference)
#include <cuda_runtime.h>
#include <math.h>

#define BB 4
#define NN 512
#define FF 256
#define EE 64
#define TILE_I 8
#define LRELU_ALPHA 0.2f
#define NEG_INF_V -1e30f

#define GEMM_CTAS 128      // 512-thr CTAs, 2 gemm tiles each (256 tiles total)
#define SCORE_CTAS 1024    // 512-thr CTAs, 2 score rows each
#define AV_CTAS 256        // 512-thr CTAs, 8 rows each

// scratch (no allocations allowed)
__device__ float g_h[BB*NN*FF];        // 2 MB
__device__ float g_sip[4*BB*NN];       // per-n-tile partial s_i
__device__ float g_sjp[4*BB*NN];       // per-n-tile partial s_j
__device__ float g_w1a3[EE];
__device__ volatile int g_flag;            // w1a3 ready
__device__ volatile int g_gemmflag[GEMM_CTAS];
__device__ volatile int g_rowflag[BB*NN];
__device__ float g_sc[BB*NN*NN];       // 4 MB raw edge scores

// ---- f32x2 packed helpers (Blackwell FFMA2) ----
__device__ __forceinline__ unsigned long long ffma2(unsigned long long a,
                                                    unsigned long long b,
                                                    unsigned long long c) {
    unsigned long long d;
    asm("fma.rn.f32x2 %0, %1, %2, %3;" : "=l"(d) : "l"(a), "l"(b), "l"(c));
    return d;
}
__device__ __forceinline__ unsigned long long pack2(float lo, float hi) {
    unsigned long long d;
    asm("mov.b64 %0, {%1, %2};" : "=l"(d) : "f"(lo), "f"(hi));
    return d;
}
__device__ __forceinline__ void unpack2(unsigned long long v, float& lo, float& hi) {
    asm("mov.b64 {%0, %1}, %2;" : "=f"(lo), "=f"(hi) : "l"(v));
}

// ================= ONE fused kernel =================
__global__ __launch_bounds__(512, 2) void fused_kernel(const float* __restrict__ X,
                                                       const float* __restrict__ Wm,
                                                       const float* __restrict__ edge,
                                                       const float* __restrict__ adj,
                                                       const float* __restrict__ W1,
                                                       const float* __restrict__ a,
                                                       float* __restrict__ out) {
    // gemm path
    __shared__ __align__(16) float As[2][16][33];
    __shared__ __align__(16) float Bs[16][68];
    // score path
    __shared__ float s_w[EE];
    __shared__ float s_sc[2][NN];
    // av path
    __shared__ __align__(16) unsigned char pool[24576];
    __shared__ float sh_sj[NN];
    __shared__ float reds[TILE_I];
    __shared__ float redm[TILE_I][2];
    __shared__ float reds2[TILE_I][2];

    const int tid = threadIdx.x;
    const int sub = tid >> 8;          // 0/1 half-block
    const int t2  = tid & 255;

    if (blockIdx.x < GEMM_CTAS) {
        // ---------------- w1a3 prologue (bid 0 only) ----------------
        if (blockIdx.x == 0) {
            if (tid < 256) {
                const int e = tid >> 2;
                const int q = tid & 3;
                const float* wrow = W1 + (size_t)e*FF + q*64;
                const float* a3   = a + 2*FF + q*64;
                float p = 0.f;
                #pragma unroll
                for (int iq = 0; iq < 16; iq++) {
                    float4 wv4 = *(const float4*)&wrow[iq*4];
                    float4 av4 = *(const float4*)&a3[iq*4];
                    p += wv4.x*av4.x + wv4.y*av4.y + wv4.z*av4.z + wv4.w*av4.w;
                }
                p += __shfl_xor_sync(0xffffffffu, p, 1);
                p += __shfl_xor_sync(0xffffffffu, p, 2);
                if (q == 0) g_w1a3[e] = p;
            }
            __syncthreads();
            if (tid == 0) {
                __threadfence();
                g_flag = 1;
            }
        }

        // ---------------- GEMM path: tile g = bid*2 + sub ----------------
        const int g   = blockIdx.x*2 + sub;
        const int bmi = g & 63;
        const int bni = g >> 6;        // same for both subs (g even/odd pair)
        const int bm  = bmi * 32;
        const int bn  = bni * 64;
        const int tx = t2 & 15;
        const int ty = t2 >> 4;
        const int ar = t2 >> 3;
        const int ac = (t2 & 7) * 2;
        const int br = t2 >> 4;
        const int bc = (t2 & 15) * 4;

        unsigned long long acc00 = 0, acc01 = 0, acc10 = 0, acc11 = 0;
        for (int k0 = 0; k0 < FF; k0 += 16) {
            float2 xa = *(const float2*)&X[(size_t)(bm + ar)*FF + k0 + ac];
            As[sub][ac][ar] = xa.x; As[sub][ac+1][ar] = xa.y;
            if (sub == 0)
                *(float4*)&Bs[br][bc] = *(const float4*)&Wm[(size_t)(k0 + br)*FF + bn + bc];
            __syncthreads();
            #pragma unroll
            for (int k = 0; k < 16; k++) {
                float a0 = As[sub][k][ty*2+0];
                float a1 = As[sub][k][ty*2+1];
                unsigned long long a0d = pack2(a0, a0);
                unsigned long long a1d = pack2(a1, a1);
                ulonglong2 bq = *(const ulonglong2*)&Bs[k][tx*4];
                acc00 = ffma2(a0d, bq.x, acc00);
                acc01 = ffma2(a0d, bq.y, acc01);
                acc10 = ffma2(a1d, bq.x, acc10);
                acc11 = ffma2(a1d, bq.y, acc11);
            }
            __syncthreads();
        }
        float c00, c01, c02, c03, c10, c11, c12, c13;
        unpack2(acc00, c00, c01); unpack2(acc01, c02, c03);
        unpack2(acc10, c10, c11); unpack2(acc11, c12, c13);
        *(float4*)&g_h[(size_t)(bm + ty*2 + 0)*FF + bn + tx*4] = make_float4(c00, c01, c02, c03);
        *(float4*)&g_h[(size_t)(bm + ty*2 + 1)*FF + bn + tx*4] = make_float4(c10, c11, c12, c13);

        const float4 a1v = *(const float4*)&a[bn + tx*4];
        const float4 a2v = *(const float4*)&a[FF + bn + tx*4];
        float pi0 = c00*a1v.x + c01*a1v.y + c02*a1v.z + c03*a1v.w;
        float pi1 = c10*a1v.x + c11*a1v.y + c12*a1v.z + c13*a1v.w;
        float pj0 = c00*a2v.x + c01*a2v.y + c02*a2v.z + c03*a2v.w;
        float pj1 = c10*a2v.x + c11*a2v.y + c12*a2v.z + c13*a2v.w;
        #pragma unroll
        for (int o = 8; o > 0; o >>= 1) {
            pi0 += __shfl_xor_sync(0xffffffffu, pi0, o);
            pi1 += __shfl_xor_sync(0xffffffffu, pi1, o);
            pj0 += __shfl_xor_sync(0xffffffffu, pj0, o);
            pj1 += __shfl_xor_sync(0xffffffffu, pj1, o);
        }
        if (tx == 0) {
            g_sip[bni*(BB*NN) + bm + ty*2 + 0] = pi0;
            g_sip[bni*(BB*NN) + bm + ty*2 + 1] = pi1;
            g_sjp[bni*(BB*NN) + bm + ty*2 + 0] = pj0;
            g_sjp[bni*(BB*NN) + bm + ty*2 + 1] = pj1;
        }
        __threadfence();
        __syncthreads();
        if (tid == 0) g_gemmflag[blockIdx.x] = 1;

    } else if (blockIdx.x < GEMM_CTAS + SCORE_CTAS) {
        // ---------------- SCORE path: rows bi = (bid-128)*2 + sub ----------------
        const int bi = (blockIdx.x - GEMM_CTAS)*2 + sub;

        if (tid == 0) {
            while (g_flag == 0) __nanosleep(100);
        }
        __syncthreads();
        if (tid < EE) s_w[tid] = g_w1a3[tid];
        __syncthreads();

        const int w = t2 >> 5;
        const int lane = t2 & 31;
        const int gl = lane >> 4;
        const int l = lane & 15;
        const float4 wv = *(const float4*)&s_w[l*4];
        const float4* erow = (const float4*)(edge + (size_t)bi * NN * EE);
        const int jw = w * 64;

        #pragma unroll
        for (int t = 0; t < 8; t += 2) {
            float4 ev[8];
            #pragma unroll
            for (int tt = 0; tt < 2; tt++) {
                const int jb = jw + (t + tt)*8 + gl;
                #pragma unroll
                for (int u = 0; u < 4; u++)
                    ev[tt*4 + u] = erow[(size_t)(jb + 2*u)*16 + l];
            }
            #pragma unroll
            for (int tt = 0; tt < 2; tt++) {
                const int jb = jw + (t + tt)*8 + gl;
                #pragma unroll
                for (int u = 0; u < 4; u++) {
                    float4 e4 = ev[tt*4 + u];
                    float p = e4.x*wv.x + e4.y*wv.y + e4.z*wv.z + e4.w*wv.w;
                    p += __shfl_xor_sync(0xffffffffu, p, 8);
                    p += __shfl_xor_sync(0xffffffffu, p, 4);
                    p += __shfl_xor_sync(0xffffffffu, p, 2);
                    p += __shfl_xor_sync(0xffffffffu, p, 1);
                    if (l == 0) s_sc[sub][jb + 2*u] = p;
                }
            }
        }
        __syncthreads();
        *(float2*)&g_sc[(size_t)bi*NN + t2*2] = *(const float2*)&s_sc[sub][t2*2];
        __threadfence();
        __syncthreads();
        if (t2 == 0) g_rowflag[bi] = 1;

    } else {
        // ---------------- AV path (softmax + attn@h + elu), R14 body ----------------
        const int avb = blockIdx.x - (GEMM_CTAS + SCORE_CTAS);
        const int b   = avb >> 6;
        const int i0  = (avb & 63) * TILE_I;
        const int lane = tid & 31;
        const int w    = tid >> 5;

        // wait for producers (AV bids are last -> producers already scheduled)
        if (tid < TILE_I) {
            while (g_rowflag[b*NN + i0 + tid] == 0) __nanosleep(100);
            __threadfence();
        } else if (tid < TILE_I + GEMM_CTAS) {
            while (g_gemmflag[tid - TILE_I] == 0) __nanosleep(100);
            __threadfence();
        }
        __syncthreads();

        float2 (*sh_ap)[NN] = (float2 (*)[NN])pool;

        // sj per column
        {
            float sjv = 0.f;
            #pragma unroll
            for (int t = 0; t < 4; t++) sjv += g_sjp[t*(BB*NN) + b*NN + tid];
            sh_sj[tid] = sjv;
        }
        __syncthreads();

        // softmax: warp pair per row (r = w>>1, half hh = w&1), 8 j per thread
        {
            const int r  = w >> 1;
            const int hh = w & 1;
            const int j0 = hh*256 + lane;
            float si = 0.f;
            #pragma unroll
            for (int t = 0; t < 4; t++) si += g_sip[t*(BB*NN) + b*NN + i0 + r];
            const float* scr = g_sc + (size_t)(b*NN + i0 + r)*NN;
            const float* adr = adj  + (size_t)(b*NN + i0 + r)*NN;

            float e8[8];
            float mx = NEG_INF_V;
            #pragma unroll
            for (int k = 0; k < 8; k++) {
                const int j = j0 + k*32;
                float e = si + sh_sj[j] + scr[j];
                e = (e >= 0.f) ? e : LRELU_ALPHA * e;
                e = (adr[j] > 0.f) ? e : NEG_INF_V;
                e8[k] = e;
                mx = fmaxf(mx, e);
            }
            #pragma unroll
            for (int o = 16; o > 0; o >>= 1)
                mx = fmaxf(mx, __shfl_xor_sync(0xffffffffu, mx, o));
            if (lane == 0) redm[r][hh] = mx;
            __syncthreads();
            const float bm = fmaxf(redm[r][0], redm[r][1]);

            float sum = 0.f;
            #pragma unroll
            for (int k = 0; k < 8; k++) {
                e8[k] = __expf(e8[k] - bm);
                sum += e8[k];
            }
            #pragma unroll
            for (int o = 16; o > 0; o >>= 1)
                sum += __shfl_xor_sync(0xffffffffu, sum, o);
            if (lane == 0) reds2[r][hh] = sum;

            float* base = (float*)&sh_ap[r >> 1][0];
            const int comp = r & 1;
            #pragma unroll
            for (int k = 0; k < 8; k++)
                base[(j0 + k*32)*2 + comp] = e8[k];
            __syncthreads();
            if (tid < TILE_I) reds[tid] = reds2[tid][0] + reds2[tid][1];
            __syncthreads();
        }

        // AV: 4 j-quarters x 128 fl, 2 f per thread; 8-j unrolled
        const int jq = tid >> 7;
        const int fl = tid & 127;
        unsigned long long acc0[TILE_I/2] = {};
        unsigned long long acc1[TILE_I/2] = {};
        const float* hb = g_h + (size_t)b*NN*FF;

        for (int jt = jq*128; jt < jq*128 + 128; jt += 8) {
            unsigned long long hd0[8], hd1[8];
            float h0v[8], h1v[8];
            #pragma unroll
            for (int u = 0; u < 8; u++) h0v[u] = hb[(size_t)(jt + u)*FF + fl];
            #pragma unroll
            for (int u = 0; u < 8; u++) h1v[u] = hb[(size_t)(jt + u)*FF + fl + 128];
            #pragma unroll
            for (int u = 0; u < 8; u++) { hd0[u] = pack2(h0v[u], h0v[u]); hd1[u] = pack2(h1v[u], h1v[u]); }
            #pragma unroll
            for (int rp = 0; rp < TILE_I/2; rp++) {
                ulonglong2 q0 = *(const ulonglong2*)&sh_ap[rp][jt + 0];
                ulonglong2 q1 = *(const ulonglong2*)&sh_ap[rp][jt + 2];
                ulonglong2 q2 = *(const ulonglong2*)&sh_ap[rp][jt + 4];
                ulonglong2 q3 = *(const ulonglong2*)&sh_ap[rp][jt + 6];
                acc0[rp] = ffma2(q0.x, hd0[0], acc0[rp]);
                acc0[rp] = ffma2(q0.y, hd0[1], acc0[rp]);
                acc0[rp] = ffma2(q1.x, hd0[2], acc0[rp]);
                acc0[rp] = ffma2(q1.y, hd0[3], acc0[rp]);
                acc0[rp] = ffma2(q2.x, hd0[4], acc0[rp]);
                acc0[rp] = ffma2(q2.y, hd0[5], acc0[rp]);
                acc0[rp] = ffma2(q3.x, hd0[6], acc0[rp]);
                acc0[rp] = ffma2(q3.y, hd0[7], acc0[rp]);
                acc1[rp] = ffma2(q0.x, hd1[0], acc1[rp]);
                acc1[rp] = ffma2(q0.y, hd1[1], acc1[rp]);
                acc1[rp] = ffma2(q1.x, hd1[2], acc1[rp]);
                acc1[rp] = ffma2(q1.y, hd1[3], acc1[rp]);
                acc1[rp] = ffma2(q2.x, hd1[4], acc1[rp]);
                acc1[rp] = ffma2(q2.y, hd1[5], acc1[rp]);
                acc1[rp] = ffma2(q3.x, hd1[6], acc1[rp]);
                acc1[rp] = ffma2(q3.y, hd1[7], acc1[rp]);
            }
        }

        // single-stage combine
        __syncthreads();
        float2* buf = (float2*)pool;
        if (jq > 0) {
            #pragma unroll
            for (int rp = 0; rp < TILE_I/2; rp++) {
                float lo, hi;
                unpack2(acc0[rp], lo, hi);
                buf[(((jq-1)*4 + rp)*2 + 0)*128 + fl] = make_float2(lo, hi);
                unpack2(acc1[rp], lo, hi);
                buf[(((jq-1)*4 + rp)*2 + 1)*128 + fl] = make_float2(lo, hi);
            }
        }
        __syncthreads();
        if (jq == 0) {
            #pragma unroll
            for (int rp = 0; rp < TILE_I/2; rp++) {
                const float inv0 = 1.f / reds[2*rp];
                const float inv1 = 1.f / reds[2*rp + 1];
                float2 pa0 = buf[((0*4 + rp)*2 + 0)*128 + fl];
                float2 pb0 = buf[((1*4 + rp)*2 + 0)*128 + fl];
                float2 pc0 = buf[((2*4 + rp)*2 + 0)*128 + fl];
                float2 pa1 = buf[((0*4 + rp)*2 + 1)*128 + fl];
                float2 pb1 = buf[((1*4 + rp)*2 + 1)*128 + fl];
                float2 pc1 = buf[((2*4 + rp)*2 + 1)*128 + fl];
                float lo, hi;
                unpack2(acc0[rp], lo, hi);
                float v00 = (lo + pa0.x + pb0.x + pc0.x) * inv0;
                float v01 = (hi + pa0.y + pb0.y + pc0.y) * inv1;
                unpack2(acc1[rp], lo, hi);
                float v10 = (lo + pa1.x + pb1.x + pc1.x) * inv0;
                float v11 = (hi + pa1.y + pb1.y + pc1.y) * inv1;
                out[(size_t)(b*NN + i0 + 2*rp + 0)*FF + fl]       = (v00 > 0.f) ? v00 : expm1f(v00);
                out[(size_t)(b*NN + i0 + 2*rp + 1)*FF + fl]       = (v01 > 0.f) ? v01 : expm1f(v01);
                out[(size_t)(b*NN + i0 + 2*rp + 0)*FF + fl + 128] = (v10 > 0.f) ? v10 : expm1f(v10);
                out[(size_t)(b*NN + i0 + 2*rp + 1)*FF + fl + 128] = (v11 > 0.f) ? v11 : expm1f(v11);
            }
        }
    }
}

// ================= launcher =================
extern "C" void kernel_launch(void* const* d_in, const int* in_sizes, int n_in,
                              void* d_out, int out_size) {
    const float* x    = (const float*)d_in[0];  // [4,512,256]
    const float* edge = (const float*)d_in[1];  // [4,512,512,64]
    const float* adj  = (const float*)d_in[2];  // [4,512,512]
    const float* W    = (const float*)d_in[3];  // [256,256]
    const float* W1   = (const float*)d_in[4];  // [64,256]
    const float* a    = (const float*)d_in[5];  // [768,1]
    float* out = (float*)d_out;                 // [4,512,256]

    fused_kernel<<<GEMM_CTAS + SCORE_CTAS + AV_CTAS, 512>>>(x, W, edge, adj, W1, a, out);
}